// round 7
// baseline (speedup 1.0000x reference)
#include <cuda_runtime.h>
#include <cstdint>

// Problem constants (DescrptSeA)
#define NF      2
#define NLOC    4096
#define NALL    4608
#define NROW    (NF * NLOC)
#define NNEI    138
#define SEC1    46      // type-0 neighbors: [0,46), type-1: [46,138)
#define MDIM    100
#define AXIS    16
#define NTHREADS 512
#define GRID    148

typedef unsigned long long ull;

// ---------------------------------------------------------------------------
// dtype probe: reference declares int64 indices, but JAX may emit int32.
// ---------------------------------------------------------------------------
__device__ int g_is64[2];

__global__ void probe_kernel(const unsigned* __restrict__ nlist_w,
                             const unsigned* __restrict__ atype_w) {
    if (threadIdx.x == 0 && blockIdx.x == 0) {
        int nz = 0;
        for (int p = 0; p < 512; p++) nz += (nlist_w[2 * p + 1] != 0u);
        g_is64[0] = (nz == 0) ? 1 : 0;
        nz = 0;
        for (int p = 0; p < 512; p++) nz += (atype_w[2 * p + 1] != 0u);
        g_is64[1] = (nz == 0) ? 1 : 0;
    }
}

__device__ __forceinline__ float tanh_ap(float x) {
    float y;
    asm("tanh.approx.f32 %0, %1;" : "=f"(y) : "f"(x));
    return y;
}

// ---- packed f32x2 helpers --------------------------------------------------
__device__ __forceinline__ ull pack2(float lo, float hi) {
    ull r;
    asm("mov.b64 %0, {%1, %2};" : "=l"(r) : "f"(lo), "f"(hi));
    return r;
}
__device__ __forceinline__ ull ffma2(ull a, ull b, ull c) {
    ull d;
    asm("fma.rn.f32x2 %0, %1, %2, %3;" : "=l"(d) : "l"(a), "l"(b), "l"(c));
    return d;
}
__device__ __forceinline__ ull fadd2(ull a, ull b) {
    ull d;
    asm("add.rn.f32x2 %0, %1, %2;" : "=l"(d) : "l"(a), "l"(b));
    return d;
}
__device__ __forceinline__ float hsum2(ull a) {
    float lo, hi;
    asm("mov.b64 {%0, %1}, %2;" : "=f"(lo), "=f"(hi) : "l"(a));
    return lo + hi;
}

__device__ __forceinline__ long long load_idx(const void* p, long long i, int is64) {
    if (is64) return ((const long long*)p)[i];
    return (long long)((const int*)p)[i];
}

struct SM {
    alignas(16) float env[NNEI][4];      // normalized env rows
    alignas(16) float h1[NNEI][52];      // 50 + pad (16B rows)
    alignas(16) float h0[NNEI][28];      // 25 + zero pad (16B rows)
    alignas(16) float w1T[2][50][28];    // [t][k][j], j>=25 -> 0
    alignas(16) float w0s[2][25];
    float b0s[2][25];
    alignas(16) float xyzp[5][4][MDIM];  // stage-2 partials per chunk
    alignas(16) float xyz[4][MDIM];
};

__global__ __launch_bounds__(NTHREADS, 1)
void desc_kernel(const void* __restrict__ nlist_,
                 const float* __restrict__ coord,
                 const void* __restrict__ atype_,
                 const float* __restrict__ mean,
                 const float* __restrict__ stdv,
                 const float* __restrict__ w0,
                 const float* __restrict__ b0,
                 const float* __restrict__ w1,
                 const float* __restrict__ b1,
                 const float* __restrict__ w2,
                 const float* __restrict__ b2,
                 float* __restrict__ out)
{
    extern __shared__ unsigned char smem_raw[];
    SM& sm = *reinterpret_cast<SM*>(smem_raw);

    const int tid = threadIdx.x;
    const int is64n = g_is64[0];
    const int is64a = g_is64[1];

    // ---- one-time smem staging ------------------------------------------
    for (int x = tid; x < 50; x += NTHREADS) {
        int t = x / 25, j = x % 25;
        sm.w0s[t][j] = w0[x];
        sm.b0s[t][j] = b0[x];
    }
    // w1 transposed+padded: w1T[t][k][j] = w1[t][j][k], j>=25 -> 0
    for (int x = tid; x < 2 * 50 * 28; x += NTHREADS) {
        int t = x / (50 * 28);
        int r = x - t * 50 * 28;
        int k = r / 28, j = r - k * 28;
        sm.w1T[t][k][j] = (j < 25) ? w1[t * 1250 + j * 50 + k] : 0.0f;
    }

    // ---- stage-2 roles: (column m, chunk c), no cross-thread merge -------
    const bool s2act = (tid < 500);
    const int tt = s2act ? tid : 499;     // clamp for safe addressing
    const int m  = tt % 100;
    const int c  = tt / 100;              // 0..4
    const int mm = (m < 50) ? m : m - 50;
    int t2, sbeg2, send2;
    switch (c) {
        case 0:  t2 = 0; sbeg2 = 0;   send2 = 23;   break;
        case 1:  t2 = 0; sbeg2 = 23;  send2 = 46;   break;
        case 2:  t2 = 1; sbeg2 = 46;  send2 = 77;   break;
        case 3:  t2 = 1; sbeg2 = 77;  send2 = 108;  break;
        default: t2 = 1; sbeg2 = 108; send2 = NNEI; break;
    }

    // w2 column m for type t2, packed over k: 25 f32x2 regs.
    ull wp[25];
    {
        const float* wg = w2 + t2 * 5000 + m;
        #pragma unroll
        for (int q = 0; q < 25; q++)
            wp[q] = pack2(wg[(2 * q) * 100], wg[(2 * q + 1) * 100]);
    }
    const float b2m = b2[t2 * 100 + m];

    // ---- stage h1 roles: one k per thread, 10 neighbor segments ----------
    const bool h1act = (tid < 500);
    const int kh  = tt % 50;
    const int seg = tt / 50;              // 0..9
    int th1, hbeg, hend;
    if (seg < 3) { th1 = 0; hbeg = (seg * 46) / 3;            hend = ((seg + 1) * 46) / 3; }
    else         { th1 = 1; hbeg = 46 + ((seg - 3) * 92) / 7; hend = 46 + ((seg - 2) * 92) / 7; }
    const float b1k = b1[th1 * 50 + kh];
    const int km = (kh < 25) ? kh : kh - 25;

    __syncthreads();

    // =====================  persistent row loop  ==========================
    for (int row = blockIdx.x; row < NROW; row += GRID) {
        const int f  = row >> 12;
        const int li = row & (NLOC - 1);

        // ---- stage 1: env matrix ----------------------------------------
        const long long ci = (long long)f * NALL + li;
        if (tid < NNEI) {
            const int s0 = tid;
            const float cx = coord[ci * 3 + 0];
            const float cy = coord[ci * 3 + 1];
            const float cz = coord[ci * 3 + 2];
            const int at = (int)load_idx(atype_, ci, is64a);
            long long nb = load_idx(nlist_, (long long)row * NNEI + s0, is64n);
            bool valid = (nb >= 0);
            long long j = valid ? nb : 0;
            const float* cp = coord + ((long long)f * NALL + j) * 3;
            float dx = cp[0] - cx, dy = cp[1] - cy, dz = cp[2] - cz;
            float r = sqrtf(dx * dx + dy * dy + dz * dz);
            float uu = (r - 0.5f) * (1.0f / 5.5f);
            float vv = uu * uu * uu * (uu * (-6.0f * uu + 15.0f) - 10.0f) + 1.0f;
            float w = (r < 0.5f) ? 1.0f : ((r >= 6.0f) ? 0.0f : vv);
            if (!valid) w = 0.0f;
            float inv = 1.0f / (r + 0.01f);
            float a0 = inv * w;
            float aw = inv * inv * w;
            int base = (at * NNEI + s0) * 4;
            sm.env[s0][0] = (a0      - mean[base + 0]) / stdv[base + 0];
            sm.env[s0][1] = (dx * aw - mean[base + 1]) / stdv[base + 1];
            sm.env[s0][2] = (dy * aw - mean[base + 2]) / stdv[base + 2];
            sm.env[s0][3] = (dz * aw - mean[base + 3]) / stdv[base + 3];
        }
        __syncthreads();

        // ---- stage h0: 138 x 25 (+ zero pads to 28) ---------------------
        for (int x = tid; x < NNEI * 28; x += NTHREADS) {
            int s0 = x / 28, j = x - s0 * 28;
            int t = (s0 >= SEC1);
            sm.h0[s0][j] = (j < 25)
                ? tanh_ap(sm.env[s0][0] * sm.w0s[t][j] + sm.b0s[t][j])
                : 0.0f;
        }
        __syncthreads();

        // ---- stage h1: one k per thread, 2-neighbor unroll for ILP ------
        if (h1act) {
            ulonglong2 wk[7];
            const ulonglong2* w1p = (const ulonglong2*)&sm.w1T[th1][kh][0];
            #pragma unroll
            for (int v = 0; v < 7; v++) wk[v] = w1p[v];
            int s0 = hbeg;
            for (; s0 + 2 <= hend; s0 += 2) {
                const ulonglong2* hA = (const ulonglong2*)&sm.h0[s0][0];
                const ulonglong2* hB = (const ulonglong2*)&sm.h0[s0 + 1][0];
                ull aA0 = 0ull, aA1 = 0ull, aB0 = 0ull, aB1 = 0ull;
                #pragma unroll
                for (int v = 0; v < 7; v++) {
                    ulonglong2 ha = hA[v];
                    ulonglong2 hb = hB[v];
                    aA0 = ffma2(ha.x, wk[v].x, aA0);
                    aA1 = ffma2(ha.y, wk[v].y, aA1);
                    aB0 = ffma2(hb.x, wk[v].x, aB0);
                    aB1 = ffma2(hb.y, wk[v].y, aB1);
                }
                float accA = hsum2(fadd2(aA0, aA1)) + b1k;
                float accB = hsum2(fadd2(aB0, aB1)) + b1k;
                sm.h1[s0][kh]     = tanh_ap(accA) + sm.h0[s0][km];
                sm.h1[s0 + 1][kh] = tanh_ap(accB) + sm.h0[s0 + 1][km];
            }
            if (s0 < hend) {
                const ulonglong2* hA = (const ulonglong2*)&sm.h0[s0][0];
                ull a0 = 0ull, a1 = 0ull;
                #pragma unroll
                for (int v = 0; v < 7; v++) {
                    ulonglong2 ha = hA[v];
                    a0 = ffma2(ha.x, wk[v].x, a0);
                    a1 = ffma2(ha.y, wk[v].y, a1);
                }
                float acc = hsum2(fadd2(a0, a1)) + b1k;
                sm.h1[s0][kh] = tanh_ap(acc) + sm.h0[s0][km];
            }
        }
        __syncthreads();

        // ---- stage 2: per-thread column dot, 2-neighbor unroll ----------
        {
            float x0 = 0.f, x1 = 0.f, x2 = 0.f, x3 = 0.f;
            int s0 = sbeg2;
            for (; s0 + 2 <= send2; s0 += 2) {
                const ulonglong2* hA = (const ulonglong2*)&sm.h1[s0][0];
                const ulonglong2* hB = (const ulonglong2*)&sm.h1[s0 + 1][0];
                ull aA0 = 0ull, aA1 = 0ull, aB0 = 0ull, aB1 = 0ull;
                #pragma unroll
                for (int v = 0; v < 12; v++) {
                    ulonglong2 ha = hA[v];
                    ulonglong2 hb = hB[v];
                    aA0 = ffma2(ha.x, wp[2 * v],     aA0);
                    aA1 = ffma2(ha.y, wp[2 * v + 1], aA1);
                    aB0 = ffma2(hb.x, wp[2 * v],     aB0);
                    aB1 = ffma2(hb.y, wp[2 * v + 1], aB1);
                }
                ull lastA = *(const ull*)&sm.h1[s0][48];
                ull lastB = *(const ull*)&sm.h1[s0 + 1][48];
                aA0 = ffma2(lastA, wp[24], aA0);
                aB0 = ffma2(lastB, wp[24], aB0);
                float accA = hsum2(fadd2(aA0, aA1)) + b2m;
                float accB = hsum2(fadd2(aB0, aB1)) + b2m;
                float gA = tanh_ap(accA) + sm.h1[s0][mm];
                float gB = tanh_ap(accB) + sm.h1[s0 + 1][mm];
                float4 eA = *(const float4*)sm.env[s0];
                float4 eB = *(const float4*)sm.env[s0 + 1];
                x0 += eA.x * gA + eB.x * gB;
                x1 += eA.y * gA + eB.y * gB;
                x2 += eA.z * gA + eB.z * gB;
                x3 += eA.w * gA + eB.w * gB;
            }
            if (s0 < send2) {
                const ulonglong2* hA = (const ulonglong2*)&sm.h1[s0][0];
                ull a0 = 0ull, a1 = 0ull;
                #pragma unroll
                for (int v = 0; v < 12; v++) {
                    ulonglong2 ha = hA[v];
                    a0 = ffma2(ha.x, wp[2 * v],     a0);
                    a1 = ffma2(ha.y, wp[2 * v + 1], a1);
                }
                ull lastA = *(const ull*)&sm.h1[s0][48];
                a0 = ffma2(lastA, wp[24], a0);
                float acc = hsum2(fadd2(a0, a1)) + b2m;
                float g = tanh_ap(acc) + sm.h1[s0][mm];
                float4 e = *(const float4*)sm.env[s0];
                x0 += e.x * g;
                x1 += e.y * g;
                x2 += e.z * g;
                x3 += e.w * g;
            }
            if (s2act) {
                sm.xyzp[c][0][m] = x0;
                sm.xyzp[c][1][m] = x1;
                sm.xyzp[c][2][m] = x2;
                sm.xyzp[c][3][m] = x3;
            }
        }
        __syncthreads();

        // ---- combine partials -------------------------------------------
        if (tid < MDIM) {
            const float sc = 1.0f / (float)NNEI;
            float x0 = 0.f, x1 = 0.f, x2 = 0.f, x3 = 0.f;
            #pragma unroll
            for (int cc = 0; cc < 5; cc++) {
                x0 += sm.xyzp[cc][0][tid];
                x1 += sm.xyzp[cc][1][tid];
                x2 += sm.xyzp[cc][2][tid];
                x3 += sm.xyzp[cc][3][tid];
            }
            sm.xyz[0][tid] = x0 * sc;
            sm.xyz[1][tid] = x1 * sc;
            sm.xyz[2][tid] = x2 * sc;
            sm.xyz[3][tid] = x3 * sc;
        }
        __syncthreads();

        // ---- epilogue Gram product: 400 threads, one float4 each --------
        if (tid < 400) {
            const int mo = tid % 100;
            const int a4 = (tid / 100) * 4;
            float y0 = sm.xyz[0][mo], y1 = sm.xyz[1][mo];
            float y2 = sm.xyz[2][mo], y3 = sm.xyz[3][mo];
            float4 v;
            v.x = y0 * sm.xyz[0][a4 + 0] + y1 * sm.xyz[1][a4 + 0]
                + y2 * sm.xyz[2][a4 + 0] + y3 * sm.xyz[3][a4 + 0];
            v.y = y0 * sm.xyz[0][a4 + 1] + y1 * sm.xyz[1][a4 + 1]
                + y2 * sm.xyz[2][a4 + 1] + y3 * sm.xyz[3][a4 + 1];
            v.z = y0 * sm.xyz[0][a4 + 2] + y1 * sm.xyz[1][a4 + 2]
                + y2 * sm.xyz[2][a4 + 2] + y3 * sm.xyz[3][a4 + 2];
            v.w = y0 * sm.xyz[0][a4 + 3] + y1 * sm.xyz[1][a4 + 3]
                + y2 * sm.xyz[2][a4 + 3] + y3 * sm.xyz[3][a4 + 3];
            *(float4*)(out + (long long)row * (MDIM * AXIS) + mo * AXIS + a4) = v;
        }
        __syncthreads();
    }
}

extern "C" void kernel_launch(void* const* d_in, const int* in_sizes, int n_in,
                              void* d_out, int out_size)
{
    const void*  nlist = d_in[0];
    const float* coord = (const float*)d_in[1];
    const void*  atype = d_in[2];
    const float* mean  = (const float*)d_in[3];
    const float* stdv  = (const float*)d_in[4];
    const float* w0    = (const float*)d_in[5];
    const float* b0    = (const float*)d_in[6];
    const float* w1    = (const float*)d_in[7];
    const float* b1    = (const float*)d_in[8];
    const float* w2    = (const float*)d_in[9];
    const float* b2    = (const float*)d_in[10];
    float* out = (float*)d_out;

    cudaFuncSetAttribute(desc_kernel,
                         cudaFuncAttributeMaxDynamicSharedMemorySize,
                         (int)sizeof(SM));

    probe_kernel<<<1, 32>>>((const unsigned*)nlist, (const unsigned*)atype);
    desc_kernel<<<GRID, NTHREADS, sizeof(SM)>>>(
        nlist, coord, atype, mean, stdv, w0, b0, w1, b1, w2, b2, out);
}

// round 8
// speedup vs baseline: 1.1865x; 1.1865x over previous
#include <cuda_runtime.h>
#include <cstdint>

// Problem constants (DescrptSeA)
#define NF      2
#define NLOC    4096
#define NALL    4608
#define NROW    (NF * NLOC)
#define NNEI    138
#define SEC1    46      // type-0 neighbors: [0,46), type-1: [46,138)
#define MDIM    100
#define AXIS    16
#define NTHREADS 320
#define GRID    296     // 2 CTAs per SM x 148 SMs

typedef unsigned long long ull;

// ---------------------------------------------------------------------------
// dtype probe: reference declares int64 indices, but JAX may emit int32.
// ---------------------------------------------------------------------------
__device__ int g_is64[2];

__global__ void probe_kernel(const unsigned* __restrict__ nlist_w,
                             const unsigned* __restrict__ atype_w) {
    if (threadIdx.x == 0 && blockIdx.x == 0) {
        int nz = 0;
        for (int p = 0; p < 512; p++) nz += (nlist_w[2 * p + 1] != 0u);
        g_is64[0] = (nz == 0) ? 1 : 0;
        nz = 0;
        for (int p = 0; p < 512; p++) nz += (atype_w[2 * p + 1] != 0u);
        g_is64[1] = (nz == 0) ? 1 : 0;
    }
}

__device__ __forceinline__ float tanh_ap(float x) {
    float y;
    asm("tanh.approx.f32 %0, %1;" : "=f"(y) : "f"(x));
    return y;
}

// ---- packed f32x2 helpers --------------------------------------------------
__device__ __forceinline__ ull pack2(float lo, float hi) {
    ull r;
    asm("mov.b64 %0, {%1, %2};" : "=l"(r) : "f"(lo), "f"(hi));
    return r;
}
__device__ __forceinline__ ull ffma2(ull a, ull b, ull c) {
    ull d;
    asm("fma.rn.f32x2 %0, %1, %2, %3;" : "=l"(d) : "l"(a), "l"(b), "l"(c));
    return d;
}
__device__ __forceinline__ ull fadd2(ull a, ull b) {
    ull d;
    asm("add.rn.f32x2 %0, %1, %2;" : "=l"(d) : "l"(a), "l"(b));
    return d;
}
__device__ __forceinline__ float hsum2(ull a) {
    float lo, hi;
    asm("mov.b64 {%0, %1}, %2;" : "=f"(lo), "=f"(hi) : "l"(a));
    return lo + hi;
}

__device__ __forceinline__ long long load_idx(const void* p, long long i, int is64) {
    if (is64) return ((const long long*)p)[i];
    return (long long)((const int*)p)[i];
}

struct SM {
    alignas(16) float env[NNEI][4];      // normalized env rows
    alignas(16) float h1[NNEI][52];      // 50 + pad (16B rows)
    alignas(16) float h0[NNEI][28];      // 25 + zero pad (16B rows)
    alignas(16) float w1T[2][50][28];    // [t][k][j], j>=25 -> 0
    alignas(16) float w0s[2][25];
    float b0s[2][25];
    alignas(16) float xyzp[3][4][MDIM];  // stage-2 partials per chunk
    alignas(16) float xyz[4][MDIM];
};

__global__ __launch_bounds__(NTHREADS, 2)
void desc_kernel(const void* __restrict__ nlist_,
                 const float* __restrict__ coord,
                 const void* __restrict__ atype_,
                 const float* __restrict__ mean,
                 const float* __restrict__ stdv,
                 const float* __restrict__ w0,
                 const float* __restrict__ b0,
                 const float* __restrict__ w1,
                 const float* __restrict__ b1,
                 const float* __restrict__ w2,
                 const float* __restrict__ b2,
                 float* __restrict__ out)
{
    extern __shared__ unsigned char smem_raw[];
    SM& sm = *reinterpret_cast<SM*>(smem_raw);

    const int tid = threadIdx.x;
    const int is64n = g_is64[0];
    const int is64a = g_is64[1];

    // ---- one-time smem staging ------------------------------------------
    for (int x = tid; x < 50; x += NTHREADS) {
        int t = x / 25, j = x % 25;
        sm.w0s[t][j] = w0[x];
        sm.b0s[t][j] = b0[x];
    }
    // w1 transposed+padded: w1T[t][k][j] = w1[t][j][k], j>=25 -> 0
    for (int x = tid; x < 2 * 50 * 28; x += NTHREADS) {
        int t = x / (50 * 28);
        int r = x - t * 50 * 28;
        int k = r / 28, j = r - k * 28;
        sm.w1T[t][k][j] = (j < 25) ? w1[t * 1250 + j * 50 + k] : 0.0f;
    }

    // ---- stage-2 roles: 3 chunks x 100 columns, perfectly balanced -------
    const bool s2act = (tid < 300);
    const int tt = s2act ? tid : 299;     // clamp for safe addressing
    const int m  = tt % 100;
    const int c  = tt / 100;              // 0..2
    const int mm = (m < 50) ? m : m - 50;
    const int t2    = (c == 0) ? 0 : 1;
    const int sbeg2 = c * 46;             // 0 / 46 / 92
    const int send2 = sbeg2 + 46;         // 46 each
    const float b2m = b2[t2 * 100 + m];
    const float* wg = w2 + t2 * 5000 + m; // column base for per-row reload

    // ---- stage h1 roles: 6 segments x 50 k, perfectly balanced -----------
    const bool h1act = (tid < 300);
    const int kh  = tt % 50;
    const int seg = tt / 50;              // 0..5
    const int th1  = (seg < 2) ? 0 : 1;
    const int hbeg = seg * 23;            // contiguous 23-blocks over [0,138)
    const int hend = hbeg + 23;
    const float b1k = b1[th1 * 50 + kh];
    const int km = (kh < 25) ? kh : kh - 25;

    __syncthreads();

    // =====================  persistent row loop  ==========================
    for (int row = blockIdx.x; row < NROW; row += GRID) {
        const int f  = row >> 12;
        const int li = row & (NLOC - 1);

        // ---- stage 1: env matrix ----------------------------------------
        const long long ci = (long long)f * NALL + li;
        if (tid < NNEI) {
            const int s0 = tid;
            const float cx = coord[ci * 3 + 0];
            const float cy = coord[ci * 3 + 1];
            const float cz = coord[ci * 3 + 2];
            const int at = (int)load_idx(atype_, ci, is64a);
            long long nb = load_idx(nlist_, (long long)row * NNEI + s0, is64n);
            bool valid = (nb >= 0);
            long long j = valid ? nb : 0;
            const float* cp = coord + ((long long)f * NALL + j) * 3;
            float dx = cp[0] - cx, dy = cp[1] - cy, dz = cp[2] - cz;
            float r = sqrtf(dx * dx + dy * dy + dz * dz);
            float uu = (r - 0.5f) * (1.0f / 5.5f);
            float vv = uu * uu * uu * (uu * (-6.0f * uu + 15.0f) - 10.0f) + 1.0f;
            float w = (r < 0.5f) ? 1.0f : ((r >= 6.0f) ? 0.0f : vv);
            if (!valid) w = 0.0f;
            float inv = 1.0f / (r + 0.01f);
            float a0 = inv * w;
            float aw = inv * inv * w;
            int base = (at * NNEI + s0) * 4;
            sm.env[s0][0] = (a0      - mean[base + 0]) / stdv[base + 0];
            sm.env[s0][1] = (dx * aw - mean[base + 1]) / stdv[base + 1];
            sm.env[s0][2] = (dy * aw - mean[base + 2]) / stdv[base + 2];
            sm.env[s0][3] = (dz * aw - mean[base + 3]) / stdv[base + 3];
        }
        __syncthreads();

        // ---- stage h0: 138 x 25 (+ zero pads to 28) ---------------------
        for (int x = tid; x < NNEI * 28; x += NTHREADS) {
            int s0 = x / 28, j = x - s0 * 28;
            int t = (s0 >= SEC1);
            sm.h0[s0][j] = (j < 25)
                ? tanh_ap(sm.env[s0][0] * sm.w0s[t][j] + sm.b0s[t][j])
                : 0.0f;
        }
        __syncthreads();

        // ---- stage h1: one k per thread, wk hoisted per row -------------
        if (h1act) {
            ulonglong2 wk[7];
            const ulonglong2* w1p = (const ulonglong2*)&sm.w1T[th1][kh][0];
            #pragma unroll
            for (int v = 0; v < 7; v++) wk[v] = w1p[v];
            for (int s0 = hbeg; s0 < hend; s0++) {
                const ulonglong2* h0p = (const ulonglong2*)&sm.h0[s0][0];
                ull a0 = 0ull, a1 = 0ull;
                #pragma unroll
                for (int v = 0; v < 7; v++) {
                    ulonglong2 h = h0p[v];
                    a0 = ffma2(h.x, wk[v].x, a0);
                    a1 = ffma2(h.y, wk[v].y, a1);
                }
                float acc = hsum2(fadd2(a0, a1)) + b1k;
                sm.h1[s0][kh] = tanh_ap(acc) + sm.h0[s0][km];
            }
        }
        __syncthreads();

        // ---- stage 2: per-thread column dot; wp reloaded per row --------
        {
            // w2 column m packed over k: 25 f32x2 regs. Reloaded each row so
            // the 50 registers are not live during stage h1 (keeps peak regs
            // under the 2-CTA cap). Loads are lane-coalesced and L1-hot.
            ull wp[25];
            #pragma unroll
            for (int q = 0; q < 25; q++)
                wp[q] = pack2(wg[(2 * q) * 100], wg[(2 * q + 1) * 100]);

            ull x01 = 0ull, x23 = 0ull;
            for (int s0 = sbeg2; s0 < send2; s0++) {
                const ulonglong2* hp = (const ulonglong2*)&sm.h1[s0][0];
                ull a0 = 0ull, a1 = 0ull;
                #pragma unroll
                for (int v = 0; v < 12; v++) {
                    ulonglong2 h = hp[v];
                    a0 = ffma2(h.x, wp[2 * v],     a0);
                    a1 = ffma2(h.y, wp[2 * v + 1], a1);
                }
                ull last = *(const ull*)&sm.h1[s0][48];
                a0 = ffma2(last, wp[24], a0);
                float acc = hsum2(fadd2(a0, a1)) + b2m;
                float g = tanh_ap(acc) + sm.h1[s0][mm];
                ull g2 = pack2(g, g);
                const ull* ep = (const ull*)sm.env[s0];
                x01 = ffma2(ep[0], g2, x01);
                x23 = ffma2(ep[1], g2, x23);
            }
            if (s2act) {
                float e0, e1, e2, e3;
                asm("mov.b64 {%0, %1}, %2;" : "=f"(e0), "=f"(e1) : "l"(x01));
                asm("mov.b64 {%0, %1}, %2;" : "=f"(e2), "=f"(e3) : "l"(x23));
                sm.xyzp[c][0][m] = e0;
                sm.xyzp[c][1][m] = e1;
                sm.xyzp[c][2][m] = e2;
                sm.xyzp[c][3][m] = e3;
            }
        }
        __syncthreads();

        // ---- combine partials -------------------------------------------
        if (tid < MDIM) {
            const float sc = 1.0f / (float)NNEI;
            float x0 = 0.f, x1 = 0.f, x2 = 0.f, x3 = 0.f;
            #pragma unroll
            for (int cc = 0; cc < 3; cc++) {
                x0 += sm.xyzp[cc][0][tid];
                x1 += sm.xyzp[cc][1][tid];
                x2 += sm.xyzp[cc][2][tid];
                x3 += sm.xyzp[cc][3][tid];
            }
            sm.xyz[0][tid] = x0 * sc;
            sm.xyz[1][tid] = x1 * sc;
            sm.xyz[2][tid] = x2 * sc;
            sm.xyz[3][tid] = x3 * sc;
        }
        __syncthreads();

        // ---- epilogue Gram product: 400 items over 320 threads ----------
        for (int item = tid; item < 400; item += NTHREADS) {
            const int mo = item % 100;
            const int a4 = (item / 100) * 4;
            float y0 = sm.xyz[0][mo], y1 = sm.xyz[1][mo];
            float y2 = sm.xyz[2][mo], y3 = sm.xyz[3][mo];
            float4 v;
            v.x = y0 * sm.xyz[0][a4 + 0] + y1 * sm.xyz[1][a4 + 0]
                + y2 * sm.xyz[2][a4 + 0] + y3 * sm.xyz[3][a4 + 0];
            v.y = y0 * sm.xyz[0][a4 + 1] + y1 * sm.xyz[1][a4 + 1]
                + y2 * sm.xyz[2][a4 + 1] + y3 * sm.xyz[3][a4 + 1];
            v.z = y0 * sm.xyz[0][a4 + 2] + y1 * sm.xyz[1][a4 + 2]
                + y2 * sm.xyz[2][a4 + 2] + y3 * sm.xyz[3][a4 + 2];
            v.w = y0 * sm.xyz[0][a4 + 3] + y1 * sm.xyz[1][a4 + 3]
                + y2 * sm.xyz[2][a4 + 3] + y3 * sm.xyz[3][a4 + 3];
            *(float4*)(out + (long long)row * (MDIM * AXIS) + mo * AXIS + a4) = v;
        }
        __syncthreads();
    }
}

extern "C" void kernel_launch(void* const* d_in, const int* in_sizes, int n_in,
                              void* d_out, int out_size)
{
    const void*  nlist = d_in[0];
    const float* coord = (const float*)d_in[1];
    const void*  atype = d_in[2];
    const float* mean  = (const float*)d_in[3];
    const float* stdv  = (const float*)d_in[4];
    const float* w0    = (const float*)d_in[5];
    const float* b0    = (const float*)d_in[6];
    const float* w1    = (const float*)d_in[7];
    const float* b1    = (const float*)d_in[8];
    const float* w2    = (const float*)d_in[9];
    const float* b2    = (const float*)d_in[10];
    float* out = (float*)d_out;

    cudaFuncSetAttribute(desc_kernel,
                         cudaFuncAttributeMaxDynamicSharedMemorySize,
                         (int)sizeof(SM));

    probe_kernel<<<1, 32>>>((const unsigned*)nlist, (const unsigned*)atype);
    desc_kernel<<<GRID, NTHREADS, sizeof(SM)>>>(
        nlist, coord, atype, mean, stdv, w0, b0, w1, b1, w2, b2, out);
}